// round 8
// baseline (speedup 1.0000x reference)
#include <cuda_runtime.h>
#include <stdint.h>

#define NUM_CLASSES 100000
#define EMBED_DIM   512
#define BATCH       16384
#define NWORDS      (NUM_CLASSES / 32)   // 3125 bitmask words / fused blocks

// Self-cleaning scratch (zero-initialized; every call restores zeros).
__device__ unsigned g_touched[NWORDS];   // bit set => class touched this call
__device__ int g_head[NUM_CLASSES];      // idx+1 of chain head, 0 = empty
__device__ int g_next[BATCH];            // idx+1 of next in chain, 0 = end

// ---------------------------------------------------------------------------
// K1: build per-class chains + touched bitmask + zero loss slot
// ---------------------------------------------------------------------------
__global__ void build_kernel(const int* __restrict__ labels,
                             float* __restrict__ out) {
    int i = blockIdx.x * blockDim.x + threadIdx.x;
    if (i == 0) out[0] = 0.0f;
    if (i < BATCH) {
        int l = labels[i];
        g_next[i] = atomicExch(&g_head[l], i + 1);
        atomicOr(&g_touched[l >> 5], 1u << (l & 31));
    }
}

// ---------------------------------------------------------------------------
// K2 (fused): 3125 blocks, one bitmask word (32 class rows) each.
// Untouched rows: streamed copy. Touched rows: chain-walk update + loss.
// Block owns its word exclusively => race-free self-cleaning.
// ---------------------------------------------------------------------------
__global__ __launch_bounds__(128)
void fused_kernel(const float* __restrict__ features,
                  const float* __restrict__ center_var,
                  float* __restrict__ out) {   // out[0]=loss, out+1=centers
    const int t = threadIdx.x;
    const int word = blockIdx.x;
    const unsigned w = g_touched[word];
    const int base = word * 32;
    float* outc = out + 1;
    float lossp = 0.0f;

    // -------- copy helper (float4, 16B-aligned stores into out+1) ----------
    auto copy_row = [&](int row) {
        const float4* src =
            reinterpret_cast<const float4*>(center_var + (size_t)row * EMBED_DIM);
        float* dst = outc + (size_t)row * EMBED_DIM;
        float4 a4 = __ldcs(&src[t]);
        if (t < 127) {
            float4 b4 = __ldcs(&src[t + 1]);          // L1-hit overlap
            __stcs(reinterpret_cast<float4*>(dst + 3 + 4 * t),
                   make_float4(a4.w, b4.x, b4.y, b4.z));
        } else {
            float4 h = src[0];                        // L1 hit (lane 0's line)
            dst[0] = h.x; dst[1] = h.y; dst[2] = h.z;
            dst[511] = a4.w;                          // a4 = floats 508..511
        }
    };

    // -------- update helper (stride-128 scalar interleave, no SMEM) --------
    auto update_row = [&](int row) {
        const float* cr = center_var + (size_t)row * EMBED_DIM;
        float c0 = cr[t], c1 = cr[t + 128], c2 = cr[t + 256], c3 = cr[t + 384];
        float s0 = 0.f, s1 = 0.f, s2 = 0.f, s3 = 0.f;
        int n = 0;
        for (int j = g_head[row]; j != 0; j = g_next[j - 1]) {
            const float* fr = features + (size_t)(j - 1) * EMBED_DIM;
            float f0 = fr[t], f1 = fr[t + 128], f2 = fr[t + 256], f3 = fr[t + 384];
            float d0 = f0 - c0, d1 = f1 - c1, d2 = f2 - c2, d3 = f3 - c3;
            lossp += d0 * d0 + d1 * d1 + d2 * d2 + d3 * d3;
            s0 += f0; s1 += f1; s2 += f2; s3 += f3;
            n++;
        }
        const float a = 0.05f, fn = (float)n;
        float* dr = outc + (size_t)row * EMBED_DIM;   // scalar stores: coalesced
        dr[t]       = c0 + a * (s0 - fn * c0);
        dr[t + 128] = c1 + a * (s1 - fn * c1);
        dr[t + 256] = c2 + a * (s2 - fn * c2);
        dr[t + 384] = c3 + a * (s3 - fn * c3);
    };

    if (w == 0) {
        // common fast path: all 32 rows untouched, branchless unrolled stream
        #pragma unroll 4
        for (int r = 0; r < 32; r++) copy_row(base + r);
        return;
    }

    for (int r = 0; r < 32; r++) {
        if ((w >> r) & 1) update_row(base + r);
        else              copy_row(base + r);
    }

    // all reads of g_head/g_next complete before the clears below
    __syncthreads();

    // block-reduce loss, one atomic per touched block
    #pragma unroll
    for (int off = 16; off > 0; off >>= 1)
        lossp += __shfl_down_sync(0xFFFFFFFFu, lossp, off);
    __shared__ float ws[4];
    if ((t & 31) == 0) ws[t >> 5] = lossp;
    __syncthreads();
    if (t == 0) {
        const float inv_n = 1.0f / ((float)BATCH * (float)EMBED_DIM);
        atomicAdd(out, (ws[0] + ws[1] + ws[2] + ws[3]) * inv_n);
        g_touched[word] = 0;                          // self-clean mask
    }
    if (t < 32 && ((w >> t) & 1)) g_head[base + t] = 0;  // self-clean heads
}

// ---------------------------------------------------------------------------
// Launch
// ---------------------------------------------------------------------------
extern "C" void kernel_launch(void* const* d_in, const int* in_sizes, int n_in,
                              void* d_out, int out_size) {
    const float* features   = (const float*)d_in[0];
    const int*   labels     = (const int*)d_in[1];
    const float* center_var = (const float*)d_in[2];
    float* out = (float*)d_out;

    build_kernel<<<(BATCH + 255) / 256, 256>>>(labels, out);
    fused_kernel<<<NWORDS, 128>>>(features, center_var, out);
}

// round 9
// speedup vs baseline: 1.2523x; 1.2523x over previous
#include <cuda_runtime.h>
#include <stdint.h>

#define NUM_CLASSES 100000
#define EMBED_DIM   512
#define BATCH       16384
#define NWORDS      (NUM_CLASSES / 32)   // 3125 bitmask words
#define NCOPYB      NWORDS               // one copy block per word (32 rows)
#define NUPD        BATCH

// Self-cleaning scratch (zero-initialized by CUDA; every call restores zeros).
__device__ unsigned g_touched[NWORDS];   // bit set => class touched this call
__device__ int g_head[NUM_CLASSES];      // idx+1 of chain head, 0 = empty
__device__ int g_next[BATCH];            // idx+1 of next in chain, 0 = end

// ---------------------------------------------------------------------------
// K1: build per-class chains + touched bitmask + zero loss slot
// ---------------------------------------------------------------------------
__global__ void build_kernel(const int* __restrict__ labels,
                             float* __restrict__ out) {
    int i = blockIdx.x * blockDim.x + threadIdx.x;
    if (i == 0) out[0] = 0.0f;
    if (i < BATCH) {
        int l = labels[i];
        g_next[i] = atomicExch(&g_head[l], i + 1);
        atomicOr(&g_touched[l >> 5], 1u << (l & 31));
    }
}

// ---------------------------------------------------------------------------
// K2 (fused): blocks [0, NCOPYB) stream-copy untouched rows (heavy, first);
// blocks [NCOPYB, NCOPYB+NUPD) update touched rows + loss.
// Writes are disjoint; scratch is self-cleaned for the next call.
// ---------------------------------------------------------------------------
__global__ __launch_bounds__(128)
void fused_kernel(const float* __restrict__ features,
                  const int* __restrict__ labels,
                  const float* __restrict__ center_var,
                  float* __restrict__ out) {   // out[0]=loss, out+1=centers
    const int t = threadIdx.x;
    float* outc = out + 1;

    if (blockIdx.x < NCOPYB) {
        // ---------------- copy path: 32 contiguous rows per block ----------
        const int word = blockIdx.x;
        const unsigned w = g_touched[word];
        __syncthreads();                 // all threads have read w
        if (t == 0) g_touched[word] = 0; // self-clean (exclusive owner)

        const int base = word * 32;
        #pragma unroll 2
        for (int r = 0; r < 32; r++) {
            if (w & (1u << r)) continue;         // update path owns this row
            const int row = base + r;
            const float4* src =
                reinterpret_cast<const float4*>(center_var + (size_t)row * EMBED_DIM);
            float* dst = outc + (size_t)row * EMBED_DIM;
            float4 a4 = src[t];
            if (t < 127) {
                float4 b4 = src[t + 1];          // L1-hit overlap
                *reinterpret_cast<float4*>(dst + 3 + 4 * t) =
                    make_float4(a4.w, b4.x, b4.y, b4.z);   // 16B-aligned store
            } else {
                float4 h = src[0];
                dst[0] = h.x; dst[1] = h.y; dst[2] = h.z;
                dst[511] = a4.w;                 // a4 = floats 508..511
            }
        }
    } else {
        // ---------------- update path: one block per chain head ------------
        const int i = blockIdx.x - NCOPYB;
        const int l = labels[i];
        if (g_head[l] != i + 1) return;  // uniform; only chain head works

        const float4* crow =
            reinterpret_cast<const float4*>(center_var + (size_t)l * EMBED_DIM);
        float4 c = crow[t];

        float4 fs = make_float4(0.f, 0.f, 0.f, 0.f);
        float lossp = 0.f;
        int n = 0;

        // walk duplicate chain (length 1 for ~98% of touched classes)
        for (int j = i + 1; j != 0; j = g_next[j - 1]) {
            const float4* frow =
                reinterpret_cast<const float4*>(features + (size_t)(j - 1) * EMBED_DIM);
            float4 f = frow[t];
            float dx = f.x - c.x, dy = f.y - c.y, dz = f.z - c.z, dw = f.w - c.w;
            lossp += dx * dx + dy * dy + dz * dz + dw * dw;
            fs.x += f.x; fs.y += f.y; fs.z += f.z; fs.w += f.w;
            n++;
        }

        // new = c + 0.05 * (sum_f - n*c)
        const float a = 0.05f;
        const float fn = (float)n;
        __shared__ float srow[EMBED_DIM];
        srow[4 * t + 0] = c.x + a * (fs.x - fn * c.x);
        srow[4 * t + 1] = c.y + a * (fs.y - fn * c.y);
        srow[4 * t + 2] = c.z + a * (fs.z - fn * c.z);
        srow[4 * t + 3] = c.w + a * (fs.w - fn * c.w);
        __syncthreads();

        float* orow = outc + (size_t)l * EMBED_DIM;
        if (t < 127) {
            *reinterpret_cast<float4*>(orow + 3 + 4 * t) =
                make_float4(srow[4 * t + 3], srow[4 * t + 4],
                            srow[4 * t + 5], srow[4 * t + 6]);
        } else {
            orow[0] = srow[0]; orow[1] = srow[1]; orow[2] = srow[2];
            orow[511] = srow[511];
        }

        // block-reduce loss, single atomic per chain; self-clean head
        #pragma unroll
        for (int off = 16; off > 0; off >>= 1)
            lossp += __shfl_down_sync(0xFFFFFFFFu, lossp, off);
        __shared__ float ws[4];
        if ((t & 31) == 0) ws[t >> 5] = lossp;
        __syncthreads();
        if (t == 0) {
            const float inv_n = 1.0f / ((float)BATCH * (float)EMBED_DIM);
            atomicAdd(out, (ws[0] + ws[1] + ws[2] + ws[3]) * inv_n);
            g_head[l] = 0;               // self-clean for next call
        }
    }
}

// ---------------------------------------------------------------------------
// Launch
// ---------------------------------------------------------------------------
extern "C" void kernel_launch(void* const* d_in, const int* in_sizes, int n_in,
                              void* d_out, int out_size) {
    const float* features   = (const float*)d_in[0];
    const int*   labels     = (const int*)d_in[1];
    const float* center_var = (const float*)d_in[2];
    float* out = (float*)d_out;

    build_kernel<<<(BATCH + 255) / 256, 256>>>(labels, out);
    fused_kernel<<<NCOPYB + NUPD, 128>>>(features, labels, center_var, out);
}